// round 7
// baseline (speedup 1.0000x reference)
#include <cuda_runtime.h>
#include <cuda_bf16.h>
#include <cstdint>

#define Bx   16
#define Nn   1024
#define DINc 128
#define Hh   4
#define Dd   32
#define HD   128
#define BN   (Bx*Nn)
#define LOG2E 1.4426950408889634f

// ---------------------------------------------------------------------------
// Scratch (device globals — no allocation allowed in kernel_launch)
// ---------------------------------------------------------------------------
__device__ float    g_hT[(size_t)Bx*Hh*Nn*Dd];   // 8.4 MB tf32-rounded, [b][hh][j][d]
__device__ float    g_ei[(size_t)Hh*BN];         // [hh][row], pre-scaled by log2(e)
__device__ float    g_ej[(size_t)Hh*BN];
__device__ unsigned g_am[(size_t)32*BN];         // [jt][row] packed adjacency bits
__device__ float    g_wa[2][Hh][DINc];           // W @ a_{i,j}, pre-scaled by log2(e)
__device__ float    g_ba[2][Hh];                 // b · a_{i,j}, pre-scaled

__device__ __forceinline__ float tf32r(float x) {
    uint32_t u; asm("cvt.rna.tf32.f32 %0, %1;" : "=r"(u) : "f"(x));
    return __uint_as_float(u);
}

// ---------------------------------------------------------------------------
// Kernel 1: h = x@W + b -> g_hT (tf32, [b][hh][j][d]).
// 256 threads, 64 rows/block. W via LDG (L1-resident), x tile in smem.
// Block 0 additionally computes g_wa / g_ba (tiny; replaces k_prep).
// ---------------------------------------------------------------------------
__global__ void __launch_bounds__(256, 2) k_gemm(const float* __restrict__ x,
                                                 const float* __restrict__ W,
                                                 const float* __restrict__ bias,
                                                 const float* __restrict__ a) {
    __shared__ float4 xs4[64*32];      // 32 KB (64 rows x 128 floats)
    const int tid = threadIdx.x;
    const int c   = tid & 127;         // output column
    const int rg  = tid >> 7;          // row-group 0/1
    const size_t row0 = (size_t)blockIdx.x * 64;

    const float4* x4 = (const float4*)(x + row0*DINc);
    for (int i = tid; i < 64*32; i += 256) xs4[i] = x4[i];
    __syncthreads();

    float acc[32];
#pragma unroll
    for (int r = 0; r < 32; r++) acc[r] = 0.f;

#pragma unroll 4
    for (int k = 0; k < DINc; k += 4) {
        const float w0 = __ldg(&W[(k+0)*HD + c]);
        const float w1 = __ldg(&W[(k+1)*HD + c]);
        const float w2 = __ldg(&W[(k+2)*HD + c]);
        const float w3 = __ldg(&W[(k+3)*HD + c]);
#pragma unroll
        for (int r = 0; r < 32; r++) {
            float4 xv = xs4[(rg*32 + r)*32 + (k >> 2)];   // broadcast LDS.128
            acc[r] = fmaf(xv.x, w0, fmaf(xv.y, w1, fmaf(xv.z, w2, fmaf(xv.w, w3, acc[r]))));
        }
    }
    const int d  = c & 31, hh = c >> 5;
    const float bc = bias[c];

    const int b  = (int)(row0 >> 10);
    const int jt = (int)(((row0 >> 5) & 31) + rg);
    float* ht = g_hT + (((size_t)b*Hh + hh) << 15) + ((size_t)jt*32 << 5) + d;
#pragma unroll
    for (int r = 0; r < 32; r++) ht[r*32] = tf32r(acc[r] + bc);

    // ---- block 0: precompute wa = W@a_{i,j}, ba = b·a_{i,j} (scaled by log2e)
    if (blockIdx.x == 0 && tid < 128) {
        const int k = tid;
#pragma unroll
        for (int h2 = 0; h2 < Hh; h2++) {
            float si = 0.f, sj = 0.f;
#pragma unroll
            for (int dd = 0; dd < 32; dd++) {
                float w = __ldg(&W[k*HD + h2*32 + dd]);
                si = fmaf(w, __ldg(&a[dd]),      si);
                sj = fmaf(w, __ldg(&a[32 + dd]), sj);
            }
            g_wa[0][h2][k] = si * LOG2E;
            g_wa[1][h2][k] = sj * LOG2E;
        }
        if (k < 8) {
            const int s = k >> 2, h2 = k & 3;
            float accb = 0.f;
#pragma unroll
            for (int dd = 0; dd < 32; dd++)
                accb = fmaf(__ldg(&bias[h2*32 + dd]), __ldg(&a[s*32 + dd]), accb);
            g_ba[s][h2] = accb * LOG2E;
        }
    }
}

// ---------------------------------------------------------------------------
// Kernel 2: pack adj bits + edge logits from x (ei = x·wa_i + ba_i).
// One warp per row.
// ---------------------------------------------------------------------------
__global__ void __launch_bounds__(256) k_pack(const int* __restrict__ adj,
                                              const float* __restrict__ x) {
    const int row  = (blockIdx.x*256 + threadIdx.x) >> 5;
    const int lane = threadIdx.x & 31;

    // ---- edge logits
    const float4 xv = ((const float4*)(x + (size_t)row*DINc))[lane];
    float ev[8];
#pragma unroll
    for (int q = 0; q < 8; q++) {
        const float4 wv = *(const float4*)&g_wa[q >> 2][q & 3][lane*4];
        ev[q] = fmaf(xv.x, wv.x, fmaf(xv.y, wv.y, fmaf(xv.z, wv.z, xv.w*wv.w)));
    }
#pragma unroll
    for (int q = 0; q < 8; q++)
#pragma unroll
        for (int o = 16; o > 0; o >>= 1)
            ev[q] += __shfl_xor_sync(0xffffffffu, ev[q], o);
    if (lane == 0) {
#pragma unroll
        for (int q = 0; q < 8; q++) {
            const int s = q >> 2, hh = q & 3;
            float v = ev[q] + g_ba[s][hh];
            (s ? g_ej : g_ei)[(size_t)hh*BN + row] = v;
        }
    }

    // ---- adjacency bit pack, layout [jt-word][row]
    const int* ar = adj + (size_t)row*Nn;
#pragma unroll
    for (int wd = 0; wd < Nn/32; wd++) {
        unsigned mm = __ballot_sync(0xffffffffu, ar[wd*32 + lane] > 0);
        if (lane == 0) g_am[(size_t)wd*BN + row] = mm;
    }
}

// ---------------------------------------------------------------------------
// Kernel 3: flash attention via mma.sync.m16n8k8 tf32.
// Grid (8 i-tiles, Hh, Bx), 256 threads = 8 warps; warp owns 16 i-rows.
// P computed straight into A-fragment registers (no smem for P).
// h tile (32j x 32d) staged in double-buffered smem, one bar.sync per jt.
// ---------------------------------------------------------------------------
__global__ void __launch_bounds__(256) k_attn(float* __restrict__ out) {
    __shared__ float    ejs[Nn];          // 4 KB
    __shared__ unsigned ams[32*128];      // 16 KB  [jt][rlocal]
    __shared__ float    hs[2][32*36];     // 9.2 KB padded [j][d]

    const int tid  = threadIdx.x;
    const int lane = tid & 31;
    const int w    = tid >> 5;            // warp 0..7, owns rows w*16..w*16+15
    const int qid  = lane >> 2;           // 0..7
    const int tq   = lane & 3;            // 0..3
    const int hh   = blockIdx.y;
    const int b    = blockIdx.z;
    const int i0   = blockIdx.x * 128;
    const size_t bN = (size_t)b * Nn;

    // stage ej + masks for the whole block
    {
        const float* ejsrc = g_ej + (size_t)hh*BN + bN;
        for (int k = tid; k < Nn; k += 256) ejs[k] = ejsrc[k];
        const unsigned* amsrc = g_am + bN + i0;
        for (int k = tid; k < 32*128; k += 256)
            ams[k] = amsrc[(size_t)(k >> 7)*BN + (k & 127)];
    }

    float eir[2], lden[2];
#pragma unroll
    for (int m = 0; m < 2; m++) {
        eir[m]  = g_ei[(size_t)hh*BN + bN + i0 + w*16 + qid + 8*m];
        lden[m] = 0.f;
    }

    float acc[4][4];
#pragma unroll
    for (int nt = 0; nt < 4; nt++)
#pragma unroll
        for (int k = 0; k < 4; k++) acc[nt][k] = 0.f;

    const float* htsrc = g_hT + (((size_t)b*Hh + hh) << 15);
    float4 hv = ((const float4*)htsrc)[tid];
    __syncthreads();   // ejs/ams visible

    for (int jt = 0; jt < 32; jt++) {
        const int buf = jt & 1;
        // store prefetched h tile (padded rows: j = tid/8, d0 = (tid%8)*4)
        *(float4*)&hs[buf][(tid >> 3)*36 + (tid & 7)*4] = hv;
        __syncthreads();
        if (jt < 31)
            hv = ((const float4*)(htsrc + (size_t)(jt + 1)*1024))[tid];

        // ---- phase A: P in A-fragment layout
        const float* ej = ejs + jt*32;
        float ejv[8];
#pragma unroll
        for (int t = 0; t < 8; t++) ejv[t] = ej[tq + 4*t];
        unsigned mw[2];
#pragma unroll
        for (int m = 0; m < 2; m++) mw[m] = ams[jt*128 + w*16 + qid + 8*m];

        uint32_t pu[2][8];
#pragma unroll
        for (int m = 0; m < 2; m++) {
            const float ei = eir[m];
#pragma unroll
            for (int t = 0; t < 8; t++) {
                float e = ei + ejv[t];
                e = fmaxf(e, 0.2f*e);                       // leaky relu (log2-scaled)
                e = ((mw[m] >> (tq + 4*t)) & 1u) ? e : -10000.f;
                float p; asm("ex2.approx.ftz.f32 %0, %1;" : "=f"(p) : "f"(e));
                lden[m] += p;
                asm("cvt.rna.tf32.f32 %0, %1;" : "=r"(pu[m][t]) : "f"(p));
            }
        }

        // ---- phase B: 16 x m16n8k8 tf32 mma
#pragma unroll
        for (int ks = 0; ks < 4; ks++) {
            const float* hrow0 = &hs[buf][(ks*8 + tq)*36 + qid];
            const float* hrow1 = hrow0 + 4*36;
            const uint32_t a0 = pu[0][2*ks];
            const uint32_t a1 = pu[1][2*ks];
            const uint32_t a2 = pu[0][2*ks+1];
            const uint32_t a3 = pu[1][2*ks+1];
#pragma unroll
            for (int nt = 0; nt < 4; nt++) {
                const uint32_t b0 = __float_as_uint(hrow0[nt*8]);
                const uint32_t b1 = __float_as_uint(hrow1[nt*8]);
                asm("mma.sync.aligned.m16n8k8.row.col.f32.tf32.tf32.f32 "
                    "{%0,%1,%2,%3}, {%4,%5,%6,%7}, {%8,%9}, {%0,%1,%2,%3};"
                    : "+f"(acc[nt][0]), "+f"(acc[nt][1]),
                      "+f"(acc[nt][2]), "+f"(acc[nt][3])
                    : "r"(a0), "r"(a1), "r"(a2), "r"(a3),
                      "r"(b0), "r"(b1));
            }
        }
    }

    // ---- finish denominators (sum the 4 j-phase lanes) and store
#pragma unroll
    for (int m = 0; m < 2; m++) {
        lden[m] += __shfl_xor_sync(0xffffffffu, lden[m], 1);
        lden[m] += __shfl_xor_sync(0xffffffffu, lden[m], 2);
        lden[m] = 1.f / lden[m];
    }
#pragma unroll
    for (int half = 0; half < 2; half++) {
        const int grow = i0 + w*16 + qid + 8*half;
        const float rl = lden[half];
        float* orow = out + (bN + grow)*HD + hh*32 + tq*2;
#pragma unroll
        for (int nt = 0; nt < 4; nt++) {
            float2 v = { acc[nt][half*2 + 0]*rl, acc[nt][half*2 + 1]*rl };
            *(float2*)(orow + nt*8) = v;
        }
    }
}

// ---------------------------------------------------------------------------
extern "C" void kernel_launch(void* const* d_in, const int* in_sizes, int n_in,
                              void* d_out, int out_size) {
    const float* x = nullptr; const int* adj = nullptr;
    const float* W = nullptr; const float* bias = nullptr; const float* a = nullptr;
    for (int i = 0; i < n_in; i++) {
        switch (in_sizes[i]) {
            case Bx*Nn*DINc: x    = (const float*)d_in[i]; break;
            case Bx*Nn*Nn:   adj  = (const int*)  d_in[i]; break;
            case DINc*HD:    W    = (const float*)d_in[i]; break;
            case HD:         bias = (const float*)d_in[i]; break;
            case 2*Dd:       a    = (const float*)d_in[i]; break;
        }
    }
    k_gemm<<<BN/64, 256>>>(x, W, bias, a);
    k_pack<<<BN/8, 256>>>(adj, x);
    k_attn<<<dim3(8, Hh, Bx), 256>>>((float*)d_out);
}

// round 8
// speedup vs baseline: 1.0415x; 1.0415x over previous
#include <cuda_runtime.h>
#include <cuda_bf16.h>
#include <cstdint>

#define Bx   16
#define Nn   1024
#define DINc 128
#define Hh   4
#define Dd   32
#define HD   128
#define BN   (Bx*Nn)
#define LOG2E 1.4426950408889634f

// ---------------------------------------------------------------------------
// Scratch (device globals — no allocation allowed in kernel_launch)
// ---------------------------------------------------------------------------
__device__ float    g_hT[(size_t)Bx*Hh*Nn*Dd];   // 8.4 MB tf32-rounded, [b][hh][j][d]
__device__ float    g_ei[(size_t)Hh*BN];         // [hh][row], pre-scaled by log2(e)
__device__ float    g_ej[(size_t)Hh*BN];
__device__ unsigned g_am[(size_t)32*BN];         // [jt][row] packed adjacency bits
__device__ float    g_wa[2][Hh][DINc];           // W @ a_{i,j}, pre-scaled by log2(e)
__device__ float    g_ba[2][Hh];                 // b · a_{i,j}, pre-scaled

__device__ __forceinline__ float tf32r(float x) {
    uint32_t u; asm("cvt.rna.tf32.f32 %0, %1;" : "=r"(u) : "f"(x));
    return __uint_as_float(u);
}

#define MMA_TF32(c0,c1,c2,c3, A0,A1,A2,A3, B0,B1) \
    asm("mma.sync.aligned.m16n8k8.row.col.f32.tf32.tf32.f32 " \
        "{%0,%1,%2,%3}, {%4,%5,%6,%7}, {%8,%9}, {%0,%1,%2,%3};" \
        : "+f"(c0), "+f"(c1), "+f"(c2), "+f"(c3) \
        : "r"(A0), "r"(A1), "r"(A2), "r"(A3), "r"(B0), "r"(B1))

// ---------------------------------------------------------------------------
// Kernel 1: h = x@W + b -> g_hT via 3xTF32 mma.sync (near-fp32 accuracy).
// 256 thr = 8 warps; block tile 64 rows x 128 cols; warp = 16 rows x 64 cols.
// x tile in smem (stride 132, conflict-free); W frags via __ldg (L1-resident).
// Block 0 tail also computes g_wa / g_ba.
// ---------------------------------------------------------------------------
__global__ void __launch_bounds__(256, 2) k_gemm(const float* __restrict__ x,
                                                 const float* __restrict__ W,
                                                 const float* __restrict__ bias,
                                                 const float* __restrict__ a) {
    __shared__ __align__(16) float xs[64*132];     // 33.8 KB, row stride 132
    const int tid  = threadIdx.x;
    const int lane = tid & 31;
    const int w    = tid >> 5;
    const int qid  = lane >> 2;        // 0..7
    const int tq   = lane & 3;         // 0..3
    const int m0   = (w & 3) * 16;
    const int n0   = (w >> 2) * 64;
    const size_t row0 = (size_t)blockIdx.x * 64;

    // stage x tile: 64 rows x 128 cols, padded stride 132 (528B, 16B-aligned)
    for (int i = tid; i < 64*32; i += 256) {
        const int r = i >> 5, c4 = i & 31;
        float4 v = ((const float4*)(x + (row0 + r)*DINc))[c4];
        *(float4*)&xs[r*132 + c4*4] = v;
    }
    __syncthreads();

    float acc[8][4];
#pragma unroll
    for (int nt = 0; nt < 8; nt++)
#pragma unroll
        for (int k = 0; k < 4; k++) acc[nt][k] = 0.f;

#pragma unroll 4
    for (int ks = 0; ks < 16; ks++) {
        const int k0 = ks*8;
        // A fragment (x rows), hi/lo split
        const float av0 = xs[(m0+qid  )*132 + k0 + tq];
        const float av1 = xs[(m0+qid+8)*132 + k0 + tq];
        const float av2 = xs[(m0+qid  )*132 + k0 + tq + 4];
        const float av3 = xs[(m0+qid+8)*132 + k0 + tq + 4];
        const float ah0 = tf32r(av0), ah1 = tf32r(av1), ah2 = tf32r(av2), ah3 = tf32r(av3);
        const uint32_t Ah0 = __float_as_uint(ah0), Ah1 = __float_as_uint(ah1);
        const uint32_t Ah2 = __float_as_uint(ah2), Ah3 = __float_as_uint(ah3);
        const uint32_t Al0 = __float_as_uint(av0 - ah0), Al1 = __float_as_uint(av1 - ah1);
        const uint32_t Al2 = __float_as_uint(av2 - ah2), Al3 = __float_as_uint(av3 - ah3);

#pragma unroll
        for (int nt = 0; nt < 8; nt++) {
            const float bv0 = __ldg(&W[(k0 + tq    )*HD + n0 + nt*8 + qid]);
            const float bv1 = __ldg(&W[(k0 + tq + 4)*HD + n0 + nt*8 + qid]);
            const float bh0 = tf32r(bv0), bh1 = tf32r(bv1);
            const uint32_t Bh0 = __float_as_uint(bh0), Bh1 = __float_as_uint(bh1);
            const uint32_t Bl0 = __float_as_uint(bv0 - bh0), Bl1 = __float_as_uint(bv1 - bh1);
            MMA_TF32(acc[nt][0], acc[nt][1], acc[nt][2], acc[nt][3],
                     Ah0, Ah1, Ah2, Ah3, Bl0, Bl1);
            MMA_TF32(acc[nt][0], acc[nt][1], acc[nt][2], acc[nt][3],
                     Al0, Al1, Al2, Al3, Bh0, Bh1);
            MMA_TF32(acc[nt][0], acc[nt][1], acc[nt][2], acc[nt][3],
                     Ah0, Ah1, Ah2, Ah3, Bh0, Bh1);
        }
    }

    // epilogue: + bias, tf32 round, store to g_hT [b][hh][j][d]
    const int b = (int)(row0 >> 10);
#pragma unroll
    for (int nt = 0; nt < 8; nt++) {
        const int c0 = n0 + nt*8 + 2*tq;        // and c0+1
        const int hh = c0 >> 5, d = c0 & 31;
        const float bc0 = __ldg(&bias[c0]), bc1 = __ldg(&bias[c0 + 1]);
        float* htb = g_hT + (((size_t)b*Hh + hh) << 15) + d;
#pragma unroll
        for (int half = 0; half < 2; half++) {
            const int jj = (int)((row0 & 1023) + m0 + qid + 8*half);
            float2 v = { tf32r(acc[nt][half*2 + 0] + bc0),
                         tf32r(acc[nt][half*2 + 1] + bc1) };
            *(float2*)(htb + (size_t)jj*32) = v;
        }
    }

    // ---- block 0: precompute wa = W@a_{i,j}, ba = b·a_{i,j} (scaled by log2e)
    if (blockIdx.x == 0 && tid < 128) {
        const int k = tid;
#pragma unroll
        for (int h2 = 0; h2 < Hh; h2++) {
            float si = 0.f, sj = 0.f;
#pragma unroll
            for (int dd = 0; dd < 32; dd++) {
                float wv = __ldg(&W[k*HD + h2*32 + dd]);
                si = fmaf(wv, __ldg(&a[dd]),      si);
                sj = fmaf(wv, __ldg(&a[32 + dd]), sj);
            }
            g_wa[0][h2][k] = si * LOG2E;
            g_wa[1][h2][k] = sj * LOG2E;
        }
        if (k < 8) {
            const int s = k >> 2, h2 = k & 3;
            float accb = 0.f;
#pragma unroll
            for (int dd = 0; dd < 32; dd++)
                accb = fmaf(__ldg(&bias[h2*32 + dd]), __ldg(&a[s*32 + dd]), accb);
            g_ba[s][h2] = accb * LOG2E;
        }
    }
}

// ---------------------------------------------------------------------------
// Kernel 2: pack adj bits + edge logits from x (ei = x·wa_i + ba_i).
// One warp per row.
// ---------------------------------------------------------------------------
__global__ void __launch_bounds__(256) k_pack(const int* __restrict__ adj,
                                              const float* __restrict__ x) {
    const int row  = (blockIdx.x*256 + threadIdx.x) >> 5;
    const int lane = threadIdx.x & 31;

    // ---- edge logits
    const float4 xv = ((const float4*)(x + (size_t)row*DINc))[lane];
    float ev[8];
#pragma unroll
    for (int q = 0; q < 8; q++) {
        const float4 wv = *(const float4*)&g_wa[q >> 2][q & 3][lane*4];
        ev[q] = fmaf(xv.x, wv.x, fmaf(xv.y, wv.y, fmaf(xv.z, wv.z, xv.w*wv.w)));
    }
#pragma unroll
    for (int q = 0; q < 8; q++)
#pragma unroll
        for (int o = 16; o > 0; o >>= 1)
            ev[q] += __shfl_xor_sync(0xffffffffu, ev[q], o);
    if (lane == 0) {
#pragma unroll
        for (int q = 0; q < 8; q++) {
            const int s = q >> 2, hh = q & 3;
            float v = ev[q] + g_ba[s][hh];
            (s ? g_ej : g_ei)[(size_t)hh*BN + row] = v;
        }
    }

    // ---- adjacency bit pack, layout [jt-word][row]
    const int* ar = adj + (size_t)row*Nn;
#pragma unroll
    for (int wd = 0; wd < Nn/32; wd++) {
        unsigned mm = __ballot_sync(0xffffffffu, ar[wd*32 + lane] > 0);
        if (lane == 0) g_am[(size_t)wd*BN + row] = mm;
    }
}

// ---------------------------------------------------------------------------
// Kernel 3: flash attention via mma.sync.m16n8k8 tf32.
// Grid (8 i-tiles, Hh, Bx), 256 threads = 8 warps; warp owns 16 i-rows.
// P computed straight into A-fragment registers (no smem for P).
// h tile (32j x 32d) staged in double-buffered smem, one bar.sync per jt.
// ---------------------------------------------------------------------------
__global__ void __launch_bounds__(256) k_attn(float* __restrict__ out) {
    __shared__ float    ejs[Nn];          // 4 KB
    __shared__ unsigned ams[32*128];      // 16 KB  [jt][rlocal]
    __shared__ float    hs[2][32*36];     // 9.2 KB padded [j][d]

    const int tid  = threadIdx.x;
    const int lane = tid & 31;
    const int w    = tid >> 5;            // warp 0..7, owns rows w*16..w*16+15
    const int qid  = lane >> 2;           // 0..7
    const int tq   = lane & 3;            // 0..3
    const int hh   = blockIdx.y;
    const int b    = blockIdx.z;
    const int i0   = blockIdx.x * 128;
    const size_t bN = (size_t)b * Nn;

    // stage ej + masks for the whole block
    {
        const float* ejsrc = g_ej + (size_t)hh*BN + bN;
        for (int k = tid; k < Nn; k += 256) ejs[k] = ejsrc[k];
        const unsigned* amsrc = g_am + bN + i0;
        for (int k = tid; k < 32*128; k += 256)
            ams[k] = amsrc[(size_t)(k >> 7)*BN + (k & 127)];
    }

    float eir[2], lden[2];
#pragma unroll
    for (int m = 0; m < 2; m++) {
        eir[m]  = g_ei[(size_t)hh*BN + bN + i0 + w*16 + qid + 8*m];
        lden[m] = 0.f;
    }

    float acc[4][4];
#pragma unroll
    for (int nt = 0; nt < 4; nt++)
#pragma unroll
        for (int k = 0; k < 4; k++) acc[nt][k] = 0.f;

    const float* htsrc = g_hT + (((size_t)b*Hh + hh) << 15);
    float4 hv = ((const float4*)htsrc)[tid];
    __syncthreads();   // ejs/ams visible

    for (int jt = 0; jt < 32; jt++) {
        const int buf = jt & 1;
        // store prefetched h tile (padded rows: j = tid/8, d0 = (tid%8)*4)
        *(float4*)&hs[buf][(tid >> 3)*36 + (tid & 7)*4] = hv;
        __syncthreads();
        if (jt < 31)
            hv = ((const float4*)(htsrc + (size_t)(jt + 1)*1024))[tid];

        // ---- phase A: P in A-fragment layout
        const float* ej = ejs + jt*32;
        float ejv[8];
#pragma unroll
        for (int t = 0; t < 8; t++) ejv[t] = ej[tq + 4*t];
        unsigned mw[2];
#pragma unroll
        for (int m = 0; m < 2; m++) mw[m] = ams[jt*128 + w*16 + qid + 8*m];

        uint32_t pu[2][8];
#pragma unroll
        for (int m = 0; m < 2; m++) {
            const float ei = eir[m];
#pragma unroll
            for (int t = 0; t < 8; t++) {
                float e = ei + ejv[t];
                e = fmaxf(e, 0.2f*e);                       // leaky relu (log2-scaled)
                e = ((mw[m] >> (tq + 4*t)) & 1u) ? e : -10000.f;
                float p; asm("ex2.approx.ftz.f32 %0, %1;" : "=f"(p) : "f"(e));
                lden[m] += p;
                asm("cvt.rna.tf32.f32 %0, %1;" : "=r"(pu[m][t]) : "f"(p));
            }
        }

        // ---- phase B: 16 x m16n8k8 tf32 mma
#pragma unroll
        for (int ks = 0; ks < 4; ks++) {
            const float* hrow0 = &hs[buf][(ks*8 + tq)*36 + qid];
            const float* hrow1 = hrow0 + 4*36;
            const uint32_t a0 = pu[0][2*ks];
            const uint32_t a1 = pu[1][2*ks];
            const uint32_t a2 = pu[0][2*ks+1];
            const uint32_t a3 = pu[1][2*ks+1];
#pragma unroll
            for (int nt = 0; nt < 4; nt++) {
                const uint32_t b0 = __float_as_uint(hrow0[nt*8]);
                const uint32_t b1 = __float_as_uint(hrow1[nt*8]);
                MMA_TF32(acc[nt][0], acc[nt][1], acc[nt][2], acc[nt][3],
                         a0, a1, a2, a3, b0, b1);
            }
        }
    }

    // ---- finish denominators (sum the 4 j-phase lanes) and store
#pragma unroll
    for (int m = 0; m < 2; m++) {
        lden[m] += __shfl_xor_sync(0xffffffffu, lden[m], 1);
        lden[m] += __shfl_xor_sync(0xffffffffu, lden[m], 2);
        lden[m] = 1.f / lden[m];
    }
#pragma unroll
    for (int half = 0; half < 2; half++) {
        const int grow = i0 + w*16 + qid + 8*half;
        const float rl = lden[half];
        float* orow = out + (bN + grow)*HD + hh*32 + tq*2;
#pragma unroll
        for (int nt = 0; nt < 4; nt++) {
            float2 v = { acc[nt][half*2 + 0]*rl, acc[nt][half*2 + 1]*rl };
            *(float2*)(orow + nt*8) = v;
        }
    }
}

// ---------------------------------------------------------------------------
extern "C" void kernel_launch(void* const* d_in, const int* in_sizes, int n_in,
                              void* d_out, int out_size) {
    const float* x = nullptr; const int* adj = nullptr;
    const float* W = nullptr; const float* bias = nullptr; const float* a = nullptr;
    for (int i = 0; i < n_in; i++) {
        switch (in_sizes[i]) {
            case Bx*Nn*DINc: x    = (const float*)d_in[i]; break;
            case Bx*Nn*Nn:   adj  = (const int*)  d_in[i]; break;
            case DINc*HD:    W    = (const float*)d_in[i]; break;
            case HD:         bias = (const float*)d_in[i]; break;
            case 2*Dd:       a    = (const float*)d_in[i]; break;
        }
    }
    k_gemm<<<BN/64, 256>>>(x, W, bias, a);
    k_pack<<<BN/8, 256>>>(adj, x);
    k_attn<<<dim3(8, Hh, Bx), 256>>>((float*)d_out);
}

// round 9
// speedup vs baseline: 1.2580x; 1.2078x over previous
#include <cuda_runtime.h>
#include <cuda_bf16.h>
#include <cstdint>

#define Bx   16
#define Nn   1024
#define DINc 128
#define Hh   4
#define Dd   32
#define HD   128
#define BN   (Bx*Nn)
#define LOG2E 1.4426950408889634f

// ---------------------------------------------------------------------------
// Scratch (device globals — no allocation allowed in kernel_launch)
// ---------------------------------------------------------------------------
__device__ float    g_hT[(size_t)Bx*Hh*Nn*Dd];   // 8.4 MB tf32-rounded, [b][hh][j][d]
__device__ float    g_Ei[(size_t)Hh*BN];         // exp2(ei)      [hh][row]
__device__ float    g_Fi[(size_t)Hh*BN];         // exp2(0.2 ei)
__device__ float    g_Ej[(size_t)Hh*BN];
__device__ float    g_Fj[(size_t)Hh*BN];
__device__ unsigned g_am[(size_t)32*BN];         // [jt][row] packed adjacency bits
__device__ float    g_wa[2][Hh][DINc];           // W @ a_{i,j}, pre-scaled by log2(e)
__device__ float    g_ba[2][Hh];                 // b · a_{i,j}, pre-scaled

__device__ __forceinline__ float tf32r(float x) {
    uint32_t u; asm("cvt.rna.tf32.f32 %0, %1;" : "=r"(u) : "f"(x));
    return __uint_as_float(u);
}
__device__ __forceinline__ float ex2(float x) {
    float p; asm("ex2.approx.ftz.f32 %0, %1;" : "=f"(p) : "f"(x));
    return p;
}

#define MMA_TF32(c0,c1,c2,c3, A0,A1,A2,A3, B0,B1) \
    asm("mma.sync.aligned.m16n8k8.row.col.f32.tf32.tf32.f32 " \
        "{%0,%1,%2,%3}, {%4,%5,%6,%7}, {%8,%9}, {%0,%1,%2,%3};" \
        : "+f"(c0), "+f"(c1), "+f"(c2), "+f"(c3) \
        : "r"(A0), "r"(A1), "r"(A2), "r"(A3), "r"(B0), "r"(B1))

// ---------------------------------------------------------------------------
// Kernel 1: h = x@W + b -> g_hT via 3xTF32 mma.sync.
// Grid 512 (32 rows/block), 256 thr = 8 warps; warp = 16 rows x 32 cols.
// W fragments: 8 batched LDGs per k-step (L1-resident). x tile in smem.
// Block 0 tail computes g_wa / g_ba.
// ---------------------------------------------------------------------------
__global__ void __launch_bounds__(256, 2) k_gemm(const float* __restrict__ x,
                                                 const float* __restrict__ W,
                                                 const float* __restrict__ bias,
                                                 const float* __restrict__ a) {
    __shared__ __align__(16) float xs[32*132];     // 16.9 KB, row stride 132
    const int tid  = threadIdx.x;
    const int lane = tid & 31;
    const int w    = tid >> 5;
    const int qid  = lane >> 2;        // 0..7
    const int tq   = lane & 3;         // 0..3
    const int m0   = (w & 1) * 16;
    const int n0   = (w >> 1) * 32;
    const size_t row0 = (size_t)blockIdx.x * 32;

    // stage x tile: 32 rows x 128 cols, padded stride 132
    for (int i = tid; i < 32*32; i += 256) {
        const int r = i >> 5, c4 = i & 31;
        float4 v = ((const float4*)(x + (row0 + r)*DINc))[c4];
        *(float4*)&xs[r*132 + c4*4] = v;
    }
    __syncthreads();

    float acc[4][4];
#pragma unroll
    for (int nt = 0; nt < 4; nt++)
#pragma unroll
        for (int k = 0; k < 4; k++) acc[nt][k] = 0.f;

#pragma unroll
    for (int ks = 0; ks < 16; ks++) {
        const int k0 = ks*8;
        // batched W-fragment loads (8 LDG in flight)
        float wv0[4], wv1[4];
        const float* Wk = W + (size_t)(k0 + tq)*HD + n0 + qid;
#pragma unroll
        for (int nt = 0; nt < 4; nt++) wv0[nt] = __ldg(Wk + nt*8);
#pragma unroll
        for (int nt = 0; nt < 4; nt++) wv1[nt] = __ldg(Wk + 4*HD + nt*8);

        // A fragment (x rows), hi/lo split
        const float av0 = xs[(m0+qid  )*132 + k0 + tq];
        const float av1 = xs[(m0+qid+8)*132 + k0 + tq];
        const float av2 = xs[(m0+qid  )*132 + k0 + tq + 4];
        const float av3 = xs[(m0+qid+8)*132 + k0 + tq + 4];
        const float ah0 = tf32r(av0), ah1 = tf32r(av1), ah2 = tf32r(av2), ah3 = tf32r(av3);
        const uint32_t Ah0 = __float_as_uint(ah0), Ah1 = __float_as_uint(ah1);
        const uint32_t Ah2 = __float_as_uint(ah2), Ah3 = __float_as_uint(ah3);
        const uint32_t Al0 = __float_as_uint(av0 - ah0), Al1 = __float_as_uint(av1 - ah1);
        const uint32_t Al2 = __float_as_uint(av2 - ah2), Al3 = __float_as_uint(av3 - ah3);

#pragma unroll
        for (int nt = 0; nt < 4; nt++) {
            const float bh0 = tf32r(wv0[nt]), bh1 = tf32r(wv1[nt]);
            const uint32_t Bh0 = __float_as_uint(bh0), Bh1 = __float_as_uint(bh1);
            const uint32_t Bl0 = __float_as_uint(wv0[nt] - bh0);
            const uint32_t Bl1 = __float_as_uint(wv1[nt] - bh1);
            MMA_TF32(acc[nt][0], acc[nt][1], acc[nt][2], acc[nt][3],
                     Ah0, Ah1, Ah2, Ah3, Bl0, Bl1);
            MMA_TF32(acc[nt][0], acc[nt][1], acc[nt][2], acc[nt][3],
                     Al0, Al1, Al2, Al3, Bh0, Bh1);
            MMA_TF32(acc[nt][0], acc[nt][1], acc[nt][2], acc[nt][3],
                     Ah0, Ah1, Ah2, Ah3, Bh0, Bh1);
        }
    }

    // epilogue: + bias, tf32 round, store to g_hT [b][hh][j][d]
    const int b  = (int)(row0 >> 10);
    const int jt = (int)((row0 >> 5) & 31);
    const int hh = w >> 1;
    float* htb = g_hT + (((size_t)b*Hh + hh) << 15) + ((size_t)jt*32 << 5);
#pragma unroll
    for (int nt = 0; nt < 4; nt++) {
        const int d = nt*8 + 2*tq;
        const float bc0 = __ldg(&bias[hh*32 + d]), bc1 = __ldg(&bias[hh*32 + d + 1]);
#pragma unroll
        for (int half = 0; half < 2; half++) {
            const int jj = m0 + qid + 8*half;
            float2 v = { tf32r(acc[nt][half*2 + 0] + bc0),
                         tf32r(acc[nt][half*2 + 1] + bc1) };
            *(float2*)(htb + (size_t)jj*32 + d) = v;
        }
    }

    // ---- block 0: precompute wa = W@a_{i,j}, ba = b·a_{i,j} (scaled by log2e)
    if (blockIdx.x == 0 && tid < 128) {
        const int k = tid;
#pragma unroll
        for (int h2 = 0; h2 < Hh; h2++) {
            float si = 0.f, sj = 0.f;
#pragma unroll
            for (int dd = 0; dd < 32; dd++) {
                float wv = __ldg(&W[k*HD + h2*32 + dd]);
                si = fmaf(wv, __ldg(&a[dd]),      si);
                sj = fmaf(wv, __ldg(&a[32 + dd]), sj);
            }
            g_wa[0][h2][k] = si * LOG2E;
            g_wa[1][h2][k] = sj * LOG2E;
        }
        if (k < 8) {
            const int s = k >> 2, h2 = k & 3;
            float accb = 0.f;
#pragma unroll
            for (int dd = 0; dd < 32; dd++)
                accb = fmaf(__ldg(&bias[h2*32 + dd]), __ldg(&a[s*32 + dd]), accb);
            g_ba[s][h2] = accb * LOG2E;
        }
    }
}

// ---------------------------------------------------------------------------
// Kernel 2: pack adj bits + factored edge terms.
// ei = x·wa_i + ba_i (log2-scaled); store Ei = exp2(ei), Fi = exp2(0.2 ei),
// same for j-side. One warp per row.
// ---------------------------------------------------------------------------
__global__ void __launch_bounds__(256) k_pack(const int* __restrict__ adj,
                                              const float* __restrict__ x) {
    const int row  = (blockIdx.x*256 + threadIdx.x) >> 5;
    const int lane = threadIdx.x & 31;

    // ---- edge logits
    const float4 xv = ((const float4*)(x + (size_t)row*DINc))[lane];
    float ev[8];
#pragma unroll
    for (int q = 0; q < 8; q++) {
        const float4 wv = *(const float4*)&g_wa[q >> 2][q & 3][lane*4];
        ev[q] = fmaf(xv.x, wv.x, fmaf(xv.y, wv.y, fmaf(xv.z, wv.z, xv.w*wv.w)));
    }
#pragma unroll
    for (int q = 0; q < 8; q++)
#pragma unroll
        for (int o = 16; o > 0; o >>= 1)
            ev[q] += __shfl_xor_sync(0xffffffffu, ev[q], o);
    if (lane == 0) {
#pragma unroll
        for (int q = 0; q < 8; q++) {
            const int s = q >> 2, hh = q & 3;
            const float v = ev[q] + g_ba[s][hh];
            const size_t o = (size_t)hh*BN + row;
            if (s == 0) { g_Ei[o] = ex2(v); g_Fi[o] = ex2(0.2f*v); }
            else        { g_Ej[o] = ex2(v); g_Fj[o] = ex2(0.2f*v); }
        }
    }

    // ---- adjacency bit pack, layout [jt-word][row]
    const int* ar = adj + (size_t)row*Nn;
#pragma unroll
    for (int wd = 0; wd < Nn/32; wd++) {
        unsigned mm = __ballot_sync(0xffffffffu, ar[wd*32 + lane] > 0);
        if (lane == 0) g_am[(size_t)wd*BN + row] = mm;
    }
}

// ---------------------------------------------------------------------------
// Kernel 3: flash attention via mma.sync.m16n8k8 tf32, sync-free warps.
// Grid (8, Hh, Bx), 128 thr = 4 warps; warp owns 32 i-rows independently.
// p = max(Ei*Ej, Fi*Fj) masked — no MUFU in the hot loop.
// Per-warp-private h tile (stride 40, conflict-free B-frag LDS), __syncwarp only.
// ---------------------------------------------------------------------------
__global__ void __launch_bounds__(128, 4) k_attn(float* __restrict__ out) {
    __shared__ float EjS[Nn], FjS[Nn];     // 8 KB, t-major permuted per 32-group
    __shared__ float hsw[4][32*40];        // 20 KB, per-warp tiles

    const int tid  = threadIdx.x;
    const int lane = tid & 31;
    const int w    = tid >> 5;
    const int qid  = lane >> 2;            // 0..7
    const int tq   = lane & 3;             // 0..3
    const int hh   = blockIdx.y;
    const int b    = blockIdx.z;
    const int i0   = blockIdx.x * 128;
    const size_t bN = (size_t)b * Nn;

    // stage Ej/Fj permuted: within each 32-group, j = tq + 4t  ->  pos = tq*8 + t
    {
        const float* Ejsrc = g_Ej + (size_t)hh*BN + bN;
        const float* Fjsrc = g_Fj + (size_t)hh*BN + bN;
        for (int k = tid; k < Nn; k += 128) {
            const int pos = (k & ~31) | (((k & 3) << 3) | ((k >> 2) & 7));
            EjS[pos] = Ejsrc[k];
            FjS[pos] = Fjsrc[k];
        }
    }

    float Eir[4], Fir[4], lden[4];
#pragma unroll
    for (int m = 0; m < 4; m++) {
        const size_t o = (size_t)hh*BN + bN + i0 + w*32 + qid + 8*m;
        Eir[m] = __ldg(&g_Ei[o]);
        Fir[m] = __ldg(&g_Fi[o]);
        lden[m] = 0.f;
    }

    float acc[2][4][4];
#pragma unroll
    for (int mt = 0; mt < 2; mt++)
#pragma unroll
        for (int nt = 0; nt < 4; nt++)
#pragma unroll
            for (int k = 0; k < 4; k++) acc[mt][nt][k] = 0.f;

    const float* htsrc = g_hT + (((size_t)b*Hh + hh) << 15);
    const unsigned* amp = g_am + bN + i0 + w*32 + qid;
    float* hw = hsw[w];
    __syncthreads();   // EjS/FjS visible

    for (int jt = 0; jt < 32; jt++) {
        // masks early (in flight during phase A)
        unsigned mb[4];
#pragma unroll
        for (int m = 0; m < 4; m++)
            mb[m] = __ldg(amp + (size_t)jt*BN + 8*m) >> tq;

        // ---- phase A: P in A-fragment registers, no MUFU
        float ejt[8], fjt[8];
        *(float4*)&ejt[0] = *(const float4*)&EjS[jt*32 + tq*8];
        *(float4*)&ejt[4] = *(const float4*)&EjS[jt*32 + tq*8 + 4];
        *(float4*)&fjt[0] = *(const float4*)&FjS[jt*32 + tq*8];
        *(float4*)&fjt[4] = *(const float4*)&FjS[jt*32 + tq*8 + 4];

        uint32_t pu[4][8];
#pragma unroll
        for (int m = 0; m < 4; m++) {
#pragma unroll
            for (int t = 0; t < 8; t++) {
                float p = fmaxf(Eir[m]*ejt[t], Fir[m]*fjt[t]);
                p = (mb[m] & (1u << (4*t))) ? p : 0.f;
                lden[m] += p;
                pu[m][t] = __float_as_uint(p);   // raw fp32 -> tf32 (HW truncation)
            }
        }

        // ---- stage h tile into this warp's private buffer (no block sync)
        {
            const float4* hp = (const float4*)(htsrc + (size_t)jt*1024);
#pragma unroll
            for (int it = 0; it < 8; it++) {
                float4 v = hp[it*32 + lane];
                *(float4*)&hw[(it*4 + (lane >> 3))*40 + (lane & 7)*4] = v;
            }
        }
        __syncwarp();

        // ---- phase B: 32 x m16n8k8 tf32 mma
#pragma unroll
        for (int ksi = 0; ksi < 4; ksi++) {
            const float* h0 = &hw[(ksi*8 + tq)*40 + qid];
            const float* h1 = h0 + 4*40;
#pragma unroll
            for (int nt = 0; nt < 4; nt++) {
                const uint32_t b0 = __float_as_uint(h0[nt*8]);
                const uint32_t b1 = __float_as_uint(h1[nt*8]);
#pragma unroll
                for (int mt = 0; mt < 2; mt++) {
                    MMA_TF32(acc[mt][nt][0], acc[mt][nt][1],
                             acc[mt][nt][2], acc[mt][nt][3],
                             pu[2*mt][2*ksi], pu[2*mt+1][2*ksi],
                             pu[2*mt][2*ksi+1], pu[2*mt+1][2*ksi+1],
                             b0, b1);
                }
            }
        }
        __syncwarp();   // WAR: all reads of hw done before next jt overwrites
    }

    // ---- finish denominators (sum the 4 j-phase lanes) and store
#pragma unroll
    for (int m = 0; m < 4; m++) {
        lden[m] += __shfl_xor_sync(0xffffffffu, lden[m], 1);
        lden[m] += __shfl_xor_sync(0xffffffffu, lden[m], 2);
        lden[m] = 1.f / lden[m];
    }
#pragma unroll
    for (int mt = 0; mt < 2; mt++) {
#pragma unroll
        for (int half = 0; half < 2; half++) {
            const int m = 2*mt + half;
            const int grow = i0 + w*32 + mt*16 + qid + 8*half;
            const float rl = lden[m];
            float* orow = out + (bN + grow)*HD + hh*32 + tq*2;
#pragma unroll
            for (int nt = 0; nt < 4; nt++) {
                float2 v = { acc[mt][nt][half*2 + 0]*rl, acc[mt][nt][half*2 + 1]*rl };
                *(float2*)(orow + nt*8) = v;
            }
        }
    }
}

// ---------------------------------------------------------------------------
extern "C" void kernel_launch(void* const* d_in, const int* in_sizes, int n_in,
                              void* d_out, int out_size) {
    const float* x = nullptr; const int* adj = nullptr;
    const float* W = nullptr; const float* bias = nullptr; const float* a = nullptr;
    for (int i = 0; i < n_in; i++) {
        switch (in_sizes[i]) {
            case Bx*Nn*DINc: x    = (const float*)d_in[i]; break;
            case Bx*Nn*Nn:   adj  = (const int*)  d_in[i]; break;
            case DINc*HD:    W    = (const float*)d_in[i]; break;
            case HD:         bias = (const float*)d_in[i]; break;
            case 2*Dd:       a    = (const float*)d_in[i]; break;
        }
    }
    k_gemm<<<BN/32, 256>>>(x, W, bias, a);
    k_pack<<<BN/8, 256>>>(adj, x);
    k_attn<<<dim3(8, Hh, Bx), 128>>>((float*)d_out);
}

// round 10
// speedup vs baseline: 1.3621x; 1.0828x over previous
#include <cuda_runtime.h>
#include <cuda_bf16.h>
#include <cstdint>

#define Bx   16
#define Nn   1024
#define DINc 128
#define Hh   4
#define Dd   32
#define HD   128
#define BN   (Bx*Nn)
#define LOG2E 1.4426950408889634f

// ---------------------------------------------------------------------------
// Scratch (device globals — no allocation allowed in kernel_launch)
// ---------------------------------------------------------------------------
__device__ float    g_hT[(size_t)Bx*Hh*Nn*Dd];   // 8.4 MB tf32-rounded, [b][hh][j][d]
__device__ float    g_Ei[(size_t)Hh*BN];         // exp2(ei)      [hh][row]
__device__ float    g_Fi[(size_t)Hh*BN];         // exp2(0.2 ei)
__device__ float    g_Ej[(size_t)Hh*BN];
__device__ float    g_Fj[(size_t)Hh*BN];
__device__ unsigned g_am[(size_t)32*BN];         // [jt][row] packed adjacency bits

__device__ __forceinline__ float tf32r(float x) {
    uint32_t u; asm("cvt.rna.tf32.f32 %0, %1;" : "=r"(u) : "f"(x));
    return __uint_as_float(u);
}
__device__ __forceinline__ float ex2(float x) {
    float p; asm("ex2.approx.ftz.f32 %0, %1;" : "=f"(p) : "f"(x));
    return p;
}

#define MMA_TF32(c0,c1,c2,c3, A0,A1,A2,A3, B0,B1) \
    asm("mma.sync.aligned.m16n8k8.row.col.f32.tf32.tf32.f32 " \
        "{%0,%1,%2,%3}, {%4,%5,%6,%7}, {%8,%9}, {%0,%1,%2,%3};" \
        : "+f"(c0), "+f"(c1), "+f"(c2), "+f"(c3) \
        : "r"(A0), "r"(A1), "r"(A2), "r"(A3), "r"(B0), "r"(B1))

// ---------------------------------------------------------------------------
// Kernel 1 (fused): h = x@W + b via 3xTF32 mma.sync  ->  g_hT,
// edge logits ei/ej straight from the accumulator fragments -> g_Ei/Fi/Ej/Fj,
// and adjacency bit-packing for the same 32 rows -> g_am.
// Grid 512 (32 rows/block), 256 thr = 8 warps; warp = 16 rows x 32 cols
// (head = w>>1, row-half = w&1).
// ---------------------------------------------------------------------------
__global__ void __launch_bounds__(256, 2) k_gemm(const float* __restrict__ x,
                                                 const float* __restrict__ W,
                                                 const float* __restrict__ bias,
                                                 const float* __restrict__ a,
                                                 const int* __restrict__ adj) {
    __shared__ __align__(16) float xs[32*132];     // 16.9 KB, row stride 132
    __shared__ float as[64];
    const int tid  = threadIdx.x;
    const int lane = tid & 31;
    const int w    = tid >> 5;
    const int qid  = lane >> 2;        // 0..7
    const int tq   = lane & 3;         // 0..3
    const int m0   = (w & 1) * 16;
    const int hh   = w >> 1;
    const int n0   = hh * 32;
    const size_t row0 = (size_t)blockIdx.x * 32;

    // stage x tile + a
    for (int i = tid; i < 32*32; i += 256) {
        const int r = i >> 5, c4 = i & 31;
        float4 v = ((const float4*)(x + (row0 + r)*DINc))[c4];
        *(float4*)&xs[r*132 + c4*4] = v;
    }
    if (tid < 64) as[tid] = a[tid];
    __syncthreads();

    float acc[4][4];
#pragma unroll
    for (int nt = 0; nt < 4; nt++)
#pragma unroll
        for (int k = 0; k < 4; k++) acc[nt][k] = 0.f;

#pragma unroll
    for (int ks = 0; ks < 16; ks++) {
        const int k0 = ks*8;
        // batched W-fragment loads (8 LDG in flight, L1-resident)
        float wv0[4], wv1[4];
        const float* Wk = W + (size_t)(k0 + tq)*HD + n0 + qid;
#pragma unroll
        for (int nt = 0; nt < 4; nt++) wv0[nt] = __ldg(Wk + nt*8);
#pragma unroll
        for (int nt = 0; nt < 4; nt++) wv1[nt] = __ldg(Wk + 4*HD + nt*8);

        // A fragment (x rows), hi/lo split
        const float av0 = xs[(m0+qid  )*132 + k0 + tq];
        const float av1 = xs[(m0+qid+8)*132 + k0 + tq];
        const float av2 = xs[(m0+qid  )*132 + k0 + tq + 4];
        const float av3 = xs[(m0+qid+8)*132 + k0 + tq + 4];
        const float ah0 = tf32r(av0), ah1 = tf32r(av1), ah2 = tf32r(av2), ah3 = tf32r(av3);
        const uint32_t Ah0 = __float_as_uint(ah0), Ah1 = __float_as_uint(ah1);
        const uint32_t Ah2 = __float_as_uint(ah2), Ah3 = __float_as_uint(ah3);
        const uint32_t Al0 = __float_as_uint(av0 - ah0), Al1 = __float_as_uint(av1 - ah1);
        const uint32_t Al2 = __float_as_uint(av2 - ah2), Al3 = __float_as_uint(av3 - ah3);

#pragma unroll
        for (int nt = 0; nt < 4; nt++) {
            const float bh0 = tf32r(wv0[nt]), bh1 = tf32r(wv1[nt]);
            const uint32_t Bh0 = __float_as_uint(bh0), Bh1 = __float_as_uint(bh1);
            const uint32_t Bl0 = __float_as_uint(wv0[nt] - bh0);
            const uint32_t Bl1 = __float_as_uint(wv1[nt] - bh1);
            MMA_TF32(acc[nt][0], acc[nt][1], acc[nt][2], acc[nt][3],
                     Ah0, Ah1, Ah2, Ah3, Bl0, Bl1);
            MMA_TF32(acc[nt][0], acc[nt][1], acc[nt][2], acc[nt][3],
                     Al0, Al1, Al2, Al3, Bh0, Bh1);
            MMA_TF32(acc[nt][0], acc[nt][1], acc[nt][2], acc[nt][3],
                     Ah0, Ah1, Ah2, Ah3, Bh0, Bh1);
        }
    }

    // ---- epilogue: h = acc + bias (fp32); store tf32(h); logits from h
    const int b  = (int)(row0 >> 10);
    const int jt = (int)((row0 >> 5) & 31);
    float* htb = g_hT + (((size_t)b*Hh + hh) << 15) + ((size_t)jt*32 << 5);

    float si0 = 0.f, si1 = 0.f, sj0 = 0.f, sj1 = 0.f;
#pragma unroll
    for (int nt = 0; nt < 4; nt++) {
        const int d0 = nt*8 + 2*tq;
        const float bc0 = __ldg(&bias[n0 + d0]), bc1 = __ldg(&bias[n0 + d0 + 1]);
        const float h00 = acc[nt][0] + bc0, h01 = acc[nt][1] + bc1;   // row qid
        const float h10 = acc[nt][2] + bc0, h11 = acc[nt][3] + bc1;   // row qid+8
        const float ai0 = as[d0], ai1 = as[d0 + 1];
        const float aj0 = as[32 + d0], aj1 = as[32 + d0 + 1];
        si0 = fmaf(h00, ai0, fmaf(h01, ai1, si0));
        si1 = fmaf(h10, ai0, fmaf(h11, ai1, si1));
        sj0 = fmaf(h00, aj0, fmaf(h01, aj1, sj0));
        sj1 = fmaf(h10, aj0, fmaf(h11, aj1, sj1));
        float2 v0 = { tf32r(h00), tf32r(h01) };
        float2 v1 = { tf32r(h10), tf32r(h11) };
        *(float2*)(htb + (size_t)(m0 + qid    )*32 + d0) = v0;
        *(float2*)(htb + (size_t)(m0 + qid + 8)*32 + d0) = v1;
    }
    // reduce over the 4 tq lanes (stay within qid group: xor 1, 2)
#pragma unroll
    for (int o = 1; o <= 2; o <<= 1) {
        si0 += __shfl_xor_sync(0xffffffffu, si0, o);
        si1 += __shfl_xor_sync(0xffffffffu, si1, o);
        sj0 += __shfl_xor_sync(0xffffffffu, sj0, o);
        sj1 += __shfl_xor_sync(0xffffffffu, sj1, o);
    }
    if (tq == 0) {
        const size_t r0g = (size_t)hh*BN + row0 + m0 + qid;
        const float e0 = si0*LOG2E, e1 = si1*LOG2E;
        const float f0 = sj0*LOG2E, f1 = sj1*LOG2E;
        g_Ei[r0g]     = ex2(e0);      g_Ei[r0g + 8] = ex2(e1);
        g_Fi[r0g]     = ex2(0.2f*e0); g_Fi[r0g + 8] = ex2(0.2f*e1);
        g_Ej[r0g]     = ex2(f0);      g_Ej[r0g + 8] = ex2(f1);
        g_Fj[r0g]     = ex2(0.2f*f0); g_Fj[r0g + 8] = ex2(0.2f*f1);
    }

    // ---- adjacency bit pack: warp w packs rows row0 + w*4 .. +3
#pragma unroll
    for (int rr = 0; rr < 4; rr++) {
        const size_t row = row0 + w*4 + rr;
        const int4* arow = (const int4*)(adj + row*Nn);
#pragma unroll
        for (int c = 0; c < 8; c++) {
            const int4 v = __ldg(&arow[c*32 + lane]);
            unsigned nib = (unsigned)(v.x > 0) | ((unsigned)(v.y > 0) << 1)
                         | ((unsigned)(v.z > 0) << 2) | ((unsigned)(v.w > 0) << 3);
            nib <<= (lane & 7)*4;
            nib |= __shfl_xor_sync(0xffffffffu, nib, 1);
            nib |= __shfl_xor_sync(0xffffffffu, nib, 2);
            nib |= __shfl_xor_sync(0xffffffffu, nib, 4);
            if ((lane & 7) == 0)
                g_am[(size_t)(c*4 + (lane >> 3))*BN + row] = nib;
        }
    }
}

// ---------------------------------------------------------------------------
// Kernel 2: flash attention via mma.sync.m16n8k8 tf32, sync-free warps.
// Grid (8, Hh, Bx), 128 thr = 4 warps; warp owns 32 i-rows independently.
// p = max(Ei*Ej, Fi*Fj) masked, truncated to tf32 bits for BOTH the MMA
// numerator and the lden denominator (consistent softmax).
// ---------------------------------------------------------------------------
__global__ void __launch_bounds__(128, 4) k_attn(float* __restrict__ out) {
    __shared__ float EjS[Nn], FjS[Nn];     // 8 KB, t-major permuted per 32-group
    __shared__ float hsw[4][32*40];        // 20 KB, per-warp tiles

    const int tid  = threadIdx.x;
    const int lane = tid & 31;
    const int w    = tid >> 5;
    const int qid  = lane >> 2;            // 0..7
    const int tq   = lane & 3;             // 0..3
    const int hh   = blockIdx.y;
    const int b    = blockIdx.z;
    const int i0   = blockIdx.x * 128;
    const size_t bN = (size_t)b * Nn;

    // stage Ej/Fj permuted: within each 32-group, j = tq + 4t  ->  pos = tq*8 + t
    {
        const float* Ejsrc = g_Ej + (size_t)hh*BN + bN;
        const float* Fjsrc = g_Fj + (size_t)hh*BN + bN;
        for (int k = tid; k < Nn; k += 128) {
            const int pos = (k & ~31) | (((k & 3) << 3) | ((k >> 2) & 7));
            EjS[pos] = Ejsrc[k];
            FjS[pos] = Fjsrc[k];
        }
    }

    float Eir[4], Fir[4], lden[4];
#pragma unroll
    for (int m = 0; m < 4; m++) {
        const size_t o = (size_t)hh*BN + bN + i0 + w*32 + qid + 8*m;
        Eir[m] = __ldg(&g_Ei[o]);
        Fir[m] = __ldg(&g_Fi[o]);
        lden[m] = 0.f;
    }

    float acc[2][4][4];
#pragma unroll
    for (int mt = 0; mt < 2; mt++)
#pragma unroll
        for (int nt = 0; nt < 4; nt++)
#pragma unroll
            for (int k = 0; k < 4; k++) acc[mt][nt][k] = 0.f;

    const float* htsrc = g_hT + (((size_t)b*Hh + hh) << 15);
    const unsigned* amp = g_am + bN + i0 + w*32 + qid;
    float* hw = hsw[w];
    __syncthreads();   // EjS/FjS visible

    for (int jt = 0; jt < 32; jt++) {
        // masks early (in flight during phase A)
        unsigned mb[4];
#pragma unroll
        for (int m = 0; m < 4; m++)
            mb[m] = __ldg(amp + (size_t)jt*BN + 8*m) >> tq;

        // ---- phase A: P in A-fragment registers, no MUFU
        float ejt[8], fjt[8];
        *(float4*)&ejt[0] = *(const float4*)&EjS[jt*32 + tq*8];
        *(float4*)&ejt[4] = *(const float4*)&EjS[jt*32 + tq*8 + 4];
        *(float4*)&fjt[0] = *(const float4*)&FjS[jt*32 + tq*8];
        *(float4*)&fjt[4] = *(const float4*)&FjS[jt*32 + tq*8 + 4];

        uint32_t pu[4][8];
#pragma unroll
        for (int m = 0; m < 4; m++) {
#pragma unroll
            for (int t = 0; t < 8; t++) {
                float p = fmaxf(Eir[m]*ejt[t], Fir[m]*fjt[t]);
                p = (mb[m] & (1u << (4*t))) ? p : 0.f;
                const uint32_t pb = __float_as_uint(p) & 0xffffe000u;  // tf32 truncation
                lden[m] += __uint_as_float(pb);                        // consistent denom
                pu[m][t] = pb;
            }
        }

        // ---- stage h tile into this warp's private buffer (no block sync)
        {
            const float4* hp = (const float4*)(htsrc + (size_t)jt*1024);
#pragma unroll
            for (int it = 0; it < 8; it++) {
                float4 v = hp[it*32 + lane];
                *(float4*)&hw[(it*4 + (lane >> 3))*40 + (lane & 7)*4] = v;
            }
        }
        __syncwarp();

        // ---- phase B: 32 x m16n8k8 tf32 mma
#pragma unroll
        for (int ksi = 0; ksi < 4; ksi++) {
            const float* h0 = &hw[(ksi*8 + tq)*40 + qid];
            const float* h1 = h0 + 4*40;
#pragma unroll
            for (int nt = 0; nt < 4; nt++) {
                const uint32_t b0 = __float_as_uint(h0[nt*8]);
                const uint32_t b1 = __float_as_uint(h1[nt*8]);
#pragma unroll
                for (int mt = 0; mt < 2; mt++) {
                    MMA_TF32(acc[mt][nt][0], acc[mt][nt][1],
                             acc[mt][nt][2], acc[mt][nt][3],
                             pu[2*mt][2*ksi], pu[2*mt+1][2*ksi],
                             pu[2*mt][2*ksi+1], pu[2*mt+1][2*ksi+1],
                             b0, b1);
                }
            }
        }
        __syncwarp();   // WAR: all reads of hw done before next jt overwrites
    }

    // ---- finish denominators (sum the 4 j-phase lanes) and store
#pragma unroll
    for (int m = 0; m < 4; m++) {
        lden[m] += __shfl_xor_sync(0xffffffffu, lden[m], 1);
        lden[m] += __shfl_xor_sync(0xffffffffu, lden[m], 2);
        lden[m] = 1.f / lden[m];
    }
#pragma unroll
    for (int mt = 0; mt < 2; mt++) {
#pragma unroll
        for (int half = 0; half < 2; half++) {
            const int m = 2*mt + half;
            const int grow = i0 + w*32 + mt*16 + qid + 8*half;
            const float rl = lden[m];
            float* orow = out + (bN + grow)*HD + hh*32 + tq*2;
#pragma unroll
            for (int nt = 0; nt < 4; nt++) {
                float2 v = { acc[mt][nt][half*2 + 0]*rl, acc[mt][nt][half*2 + 1]*rl };
                *(float2*)(orow + nt*8) = v;
            }
        }
    }
}

// ---------------------------------------------------------------------------
extern "C" void kernel_launch(void* const* d_in, const int* in_sizes, int n_in,
                              void* d_out, int out_size) {
    const float* x = nullptr; const int* adj = nullptr;
    const float* W = nullptr; const float* bias = nullptr; const float* a = nullptr;
    for (int i = 0; i < n_in; i++) {
        switch (in_sizes[i]) {
            case Bx*Nn*DINc: x    = (const float*)d_in[i]; break;
            case Bx*Nn*Nn:   adj  = (const int*)  d_in[i]; break;
            case DINc*HD:    W    = (const float*)d_in[i]; break;
            case HD:         bias = (const float*)d_in[i]; break;
            case 2*Dd:       a    = (const float*)d_in[i]; break;
        }
    }
    k_gemm<<<BN/32, 256>>>(x, W, bias, a, adj);
    k_attn<<<dim3(8, Hh, Bx), 128>>>((float*)d_out);
}